// round 15
// baseline (speedup 1.0000x reference)
#include <cuda_runtime.h>
#include <cuda_fp16.h>

// TrilinearInterpolation, single-launch, CTA-specialized, warp work-stealing.
// d_out = [lut passthrough (107811 f32)][out (32,3,512,512) f32].
//
// CTAs [0, n1)    : smem = half2(ch0[i], ch1[i])       8 LDS/px, ch0+ch1, U1=2
// CTAs [n1, grid) : smem = half2(c2[i], c2[i+1]-c2[i]) 4 LDS/px, ch2,     U2=4
// R14 state: at the 12-LDS/px wavefront floor, 14.7% L1-idle from prologue +
// inter-SM finish spread. This round: per-warp work stealing from two global
// queues (1024-px units, next unit grabbed a full unit early so the atomic
// latency is hidden). Queues self-reset via a done-counter -> every launch
// sees counters == 0 (graph-replay safe, deterministic output).

constexpr int D   = 33;
constexpr int DD  = D * D;          // 1089
constexpr int D3  = D * D * D;      // 35937
constexpr int HW  = 512 * 512;      // 262144
constexpr int NPX = 32 * HW;        // 8388608
constexpr int SMEM_BYTES = D3 * 4;  // 143748
constexpr int BLK = 1024;

constexpr int UNIT = 1024;              // px per stolen unit (divides HW)
constexpr int NU   = NPX / UNIT;        // 8192 units per queue
constexpr int U1   = 2;                 // px/thread/iter, group 01
constexpr int IT1  = UNIT / (32 * U1);  // 16 warp-iters per unit
constexpr int U2   = 4;                 // px/thread/iter, group 2
constexpr int IT2  = UNIT / (32 * U2);  // 8 warp-iters per unit

// Work-stealing state (self-resetting; zero-initialized at module load).
__device__ unsigned g_q[2];
__device__ unsigned g_done[2];

__device__ __forceinline__ unsigned grab(int g, int lane)
{
    unsigned v = 0;
    if (lane == 0) v = atomicAdd(&g_q[g], 1u);
    return __shfl_sync(0xffffffffu, v, 0);
}

__device__ __forceinline__ void finish(int g, int lane, unsigned total)
{
    if (lane == 0) {
        __threadfence();                         // order prior q-atomics
        if (atomicAdd(&g_done[g], 1u) + 1 == total) {
            g_q[g] = 0u;                         // reset for next launch
            __threadfence();
            g_done[g] = 0u;
        }
    }
}

// Exact-equivalent of reference clip/floor for r >= 0 inputs:
// x = clip(r*32,0,32); x0 = clip(floor(x),0,31); w = x-x0.
__device__ __forceinline__ void coords(float r, float g, float b,
                                       int& base, float& wx, float& wy, float& wz)
{
    float x = __saturatef(r) * 32.0f;
    float y = __saturatef(g) * 32.0f;
    float z = __saturatef(b) * 32.0f;
    int ix = min((int)x, 31);           // trunc == floor (x >= 0)
    int iy = min((int)y, 31);
    int iz = min((int)z, 31);
    wx = x - (float)ix;
    wy = y - (float)iy;
    wz = z - (float)iz;
    base = iz * DD + iy * D + ix;
}

struct Px1 { float r[U1], g[U1], b[U1]; };
struct Px2 { float r[U2], g[U2], b[U2]; };

// px0 = first pixel of this warp-iter (UNIT divides HW -> whole iter in one plane).
__device__ __forceinline__ Px1 load1(const float* __restrict__ img, int px0, int lane)
{
    Px1 p;
    const int ib = ((px0 >> 18) * 3) << 18;
    const int hw = (px0 & (HW - 1)) + lane;
    #pragma unroll
    for (int k = 0; k < U1; ++k) {
        p.r[k] = __ldg(img + ib + hw + k * 32);
        p.g[k] = __ldg(img + ib + HW + hw + k * 32);
        p.b[k] = __ldg(img + ib + 2 * HW + hw + k * 32);
    }
    return p;
}

__device__ __forceinline__ Px2 load2(const float* __restrict__ img, int px0, int lane)
{
    Px2 p;
    const int ib = ((px0 >> 18) * 3) << 18;
    const int hw = (px0 & (HW - 1)) + lane;
    #pragma unroll
    for (int k = 0; k < U2; ++k) {
        p.r[k] = __ldg(img + ib + hw + k * 32);
        p.g[k] = __ldg(img + ib + HW + hw + k * 32);
        p.b[k] = __ldg(img + ib + 2 * HW + hw + k * 32);
    }
    return p;
}

__device__ __forceinline__ void proc1(const __half2* __restrict__ st,
                                      float* __restrict__ out,
                                      int px0, int lane, const Px1& p)
{
    const int ib = ((px0 >> 18) * 3) << 18;
    const int hw = (px0 & (HW - 1)) + lane;

    int base[U1]; float wx[U1], wy[U1], wz[U1];
    #pragma unroll
    for (int k = 0; k < U1; ++k)
        coords(p.r[k], p.g[k], p.b[k], base[k], wx[k], wy[k], wz[k]);

    __half2 q[U1][8];
    #pragma unroll
    for (int k = 0; k < U1; ++k) {      // all 16 LDS back-to-back
        int bse = base[k];
        q[k][0] = st[bse];          q[k][1] = st[bse + 1];
        q[k][2] = st[bse + D];      q[k][3] = st[bse + D + 1];
        q[k][4] = st[bse + DD];     q[k][5] = st[bse + DD + 1];
        q[k][6] = st[bse + DD + D]; q[k][7] = st[bse + DD + D + 1];
    }

    #pragma unroll
    for (int k = 0; k < U1; ++k) {
        float2 p000 = __half22float2(q[k][0]);
        float2 p001 = __half22float2(q[k][1]);
        float2 p010 = __half22float2(q[k][2]);
        float2 p011 = __half22float2(q[k][3]);
        float2 p100 = __half22float2(q[k][4]);
        float2 p101 = __half22float2(q[k][5]);
        float2 p110 = __half22float2(q[k][6]);
        float2 p111 = __half22float2(q[k][7]);

        float a00 = fmaf(wx[k], p001.x - p000.x, p000.x);
        float a01 = fmaf(wx[k], p011.x - p010.x, p010.x);
        float a10 = fmaf(wx[k], p101.x - p100.x, p100.x);
        float a11 = fmaf(wx[k], p111.x - p110.x, p110.x);
        float b0  = fmaf(wy[k], a01 - a00, a00);
        float b1  = fmaf(wy[k], a11 - a10, a10);
        float r0  = fmaf(wz[k], b1 - b0, b0);

        a00 = fmaf(wx[k], p001.y - p000.y, p000.y);
        a01 = fmaf(wx[k], p011.y - p010.y, p010.y);
        a10 = fmaf(wx[k], p101.y - p100.y, p100.y);
        a11 = fmaf(wx[k], p111.y - p110.y, p110.y);
        b0  = fmaf(wy[k], a01 - a00, a00);
        b1  = fmaf(wy[k], a11 - a10, a10);
        float r1 = fmaf(wz[k], b1 - b0, b0);

        __stcs(out + ib + hw + k * 32, r0);            // c=0 plane
        __stcs(out + ib + HW + hw + k * 32, r1);       // c=1 plane
    }
}

__device__ __forceinline__ void proc2(const __half2* __restrict__ st,
                                      float* __restrict__ out,
                                      int px0, int lane, const Px2& p)
{
    const int ib = ((px0 >> 18) * 3) << 18;
    const int hw = (px0 & (HW - 1)) + lane;

    int base[U2]; float wx[U2], wy[U2], wz[U2];
    #pragma unroll
    for (int k = 0; k < U2; ++k)
        coords(p.r[k], p.g[k], p.b[k], base[k], wx[k], wy[k], wz[k]);

    __half2 q[U2][4];
    #pragma unroll
    for (int k = 0; k < U2; ++k) {      // all 16 LDS back-to-back
        int bse = base[k];
        q[k][0] = st[bse];              // (v, v_next - v)
        q[k][1] = st[bse + D];
        q[k][2] = st[bse + DD];
        q[k][3] = st[bse + DD + D];
    }

    #pragma unroll
    for (int k = 0; k < U2; ++k) {
        float2 e00 = __half22float2(q[k][0]);
        float2 e01 = __half22float2(q[k][1]);
        float2 e10 = __half22float2(q[k][2]);
        float2 e11 = __half22float2(q[k][3]);

        float a00 = fmaf(wx[k], e00.y, e00.x);
        float a01 = fmaf(wx[k], e01.y, e01.x);
        float a10 = fmaf(wx[k], e10.y, e10.x);
        float a11 = fmaf(wx[k], e11.y, e11.x);
        float b0  = fmaf(wy[k], a01 - a00, a00);
        float b1  = fmaf(wy[k], a11 - a10, a10);

        __stcs(out + ib + 2 * HW + hw + k * 32,
               fmaf(wz[k], b1 - b0, b0));              // c=2 plane
    }
}

__global__ __launch_bounds__(BLK, 1)
void trilerp_kernel(const float* __restrict__ lut,
                    const float* __restrict__ img,
                    float* __restrict__ out_full)   // = d_out (tuple base)
{
    extern __shared__ unsigned int sm[];
    const int tid  = threadIdx.x;
    const int lane = tid & 31;
    const int n1   = ((int)gridDim.x * 129) / 200;  // 98 of 152
    const bool is01 = (int)blockIdx.x < n1;
    const unsigned warps1 = (unsigned)n1 * (BLK / 32);
    const unsigned warps2 = (unsigned)((int)gridDim.x - n1) * (BLK / 32);
    float* out = out_full + 3 * D3;                 // trilerp output region

    // LUT passthrough (grid-strided; ~0.7 elements/thread).
    for (int j = blockIdx.x * BLK + tid; j < 3 * D3; j += (int)gridDim.x * BLK)
        out_full[j] = __ldg(lut + j);

    // Stage + convert this group's table directly from the fp32 LUT.
    if (is01) {
        #pragma unroll 4
        for (int i = tid; i < D3; i += BLK) {
            __half2 h = __floats2half2_rn(__ldg(lut + i), __ldg(lut + D3 + i));
            sm[i] = *reinterpret_cast<unsigned int*>(&h);
        }
    } else {
        #pragma unroll 4
        for (int i = tid; i < D3; i += BLK) {
            float v  = __ldg(lut + 2 * D3 + i);
            float vn = (i + 1 < D3) ? __ldg(lut + 2 * D3 + i + 1) : v;
            __half2 h = __floats2half2_rn(v, vn - v);
            sm[i] = *reinterpret_cast<unsigned int*>(&h);
        }
    }

    if (is01) {
        // Grab first unit + prefetch its pixels BEFORE the staging barrier.
        unsigned u = grab(0, lane);
        Px1 cur;
        bool active = (u < NU);
        if (active) cur = load1(img, (int)u * UNIT, lane);
        __syncthreads();
        const __half2* st = reinterpret_cast<const __half2*>(sm);

        if (active) {
            unsigned un = grab(0, lane);     // next unit, a full unit early
            int it = 0;
            for (;;) {
                Px1 nxt; bool have = false;
                if (it + 1 < IT1) {
                    nxt = load1(img, (int)u * UNIT + (it + 1) * (32 * U1), lane);
                    have = true;
                } else if (un < NU) {
                    nxt = load1(img, (int)un * UNIT, lane);
                    have = true;
                }
                proc1(st, out, (int)u * UNIT + it * (32 * U1), lane, cur);
                if (!have) break;
                cur = nxt;
                if (++it == IT1) { it = 0; u = un; un = grab(0, lane); }
            }
        }
        finish(0, lane, warps1);
    } else {
        unsigned u = grab(1, lane);
        Px2 cur;
        bool active = (u < NU);
        if (active) cur = load2(img, (int)u * UNIT, lane);
        __syncthreads();
        const __half2* st = reinterpret_cast<const __half2*>(sm);

        if (active) {
            unsigned un = grab(1, lane);
            int it = 0;
            for (;;) {
                Px2 nxt; bool have = false;
                if (it + 1 < IT2) {
                    nxt = load2(img, (int)u * UNIT + (it + 1) * (32 * U2), lane);
                    have = true;
                } else if (un < NU) {
                    nxt = load2(img, (int)un * UNIT, lane);
                    have = true;
                }
                proc2(st, out, (int)u * UNIT + it * (32 * U2), lane, cur);
                if (!have) break;
                cur = nxt;
                if (++it == IT2) { it = 0; u = un; un = grab(1, lane); }
            }
        }
        finish(1, lane, warps2);
    }
}

extern "C" void kernel_launch(void* const* d_in, const int* in_sizes, int n_in,
                              void* d_out, int out_size)
{
    const float* lut = (const float*)d_in[0];
    const float* img = (const float*)d_in[1];
    if (n_in >= 2 && in_sizes[0] > in_sizes[1]) {   // defensive input-order check
        lut = (const float*)d_in[1];
        img = (const float*)d_in[0];
    }
    float* out = (float*)d_out;

    cudaFuncSetAttribute(trilerp_kernel,
                         cudaFuncAttributeMaxDynamicSharedMemorySize, SMEM_BYTES);

    int sms = 148;
    cudaDeviceGetAttribute(&sms, cudaDevAttrMultiProcessorCount, 0);

    trilerp_kernel<<<sms, BLK, SMEM_BYTES>>>(lut, img, out);
}

// round 16
// speedup vs baseline: 1.2209x; 1.2209x over previous
#include <cuda_runtime.h>
#include <cuda_fp16.h>

// TrilinearInterpolation, single-launch, CTA-specialized (static partition).
// d_out = [lut passthrough (107811 f32)][out (32,3,512,512) f32].
//
// CTAs [0, n1)    : smem = half2(ch0[i], ch1[i])       8 LDS/px, ch0+ch1, U1=2
// CTAs [n1, grid) : smem = half2(c2[i], c2[i+1]-c2[i]) 4 LDS/px, ch2,     U2=4
// R15 post-mortem: work-stealing atomics serialized at the LTS and broke L2
// locality -> reverted to R13's static stride partition (best known config).
// The 12-LDS/px random-gather wavefront floor (~47us busy) is irreducible;
// this round only trims prologue: batched staging + pre-barrier prefetch.

constexpr int D   = 33;
constexpr int DD  = D * D;          // 1089
constexpr int D3  = D * D * D;      // 35937
constexpr int HW  = 512 * 512;      // 262144
constexpr int NPX = 32 * HW;        // 8388608
constexpr int SMEM_BYTES = D3 * 4;  // 143748
constexpr int BLK = 1024;

constexpr int U1 = 2;
constexpr int STEP1 = BLK * U1;         // 2048 (divides HW)
constexpr int NB1   = NPX / STEP1;      // 4096

constexpr int U2 = 4;
constexpr int STEP2 = BLK * U2;         // 4096 (divides HW)
constexpr int NB2   = NPX / STEP2;      // 2048

// Exact-equivalent of reference clip/floor for r >= 0 inputs:
// x = clip(r*32,0,32); x0 = clip(floor(x),0,31); w = x-x0.
__device__ __forceinline__ void coords(float r, float g, float b,
                                       int& base, float& wx, float& wy, float& wz)
{
    float x = __saturatef(r) * 32.0f;
    float y = __saturatef(g) * 32.0f;
    float z = __saturatef(b) * 32.0f;
    int ix = min((int)x, 31);           // trunc == floor (x >= 0)
    int iy = min((int)y, 31);
    int iz = min((int)z, 31);
    wx = x - (float)ix;
    wy = y - (float)iy;
    wz = z - (float)iz;
    base = iz * DD + iy * D + ix;
}

struct Px1 { float r[U1], g[U1], b[U1]; };
struct Px2 { float r[U2], g[U2], b[U2]; };

__device__ __forceinline__ Px1 load1(const float* __restrict__ img, int blk, int tid)
{
    Px1 p;
    const int px0 = blk * STEP1;
    const int ib  = ((px0 >> 18) * 3) << 18;
    const int hw0 = (px0 & (HW - 1)) + tid;
    #pragma unroll
    for (int k = 0; k < U1; ++k) {
        int hw = hw0 + k * BLK;
        p.r[k] = __ldg(img + ib + hw);
        p.g[k] = __ldg(img + ib + HW + hw);
        p.b[k] = __ldg(img + ib + 2 * HW + hw);
    }
    return p;
}

__device__ __forceinline__ Px2 load2(const float* __restrict__ img, int blk, int tid)
{
    Px2 p;
    const int px0 = blk * STEP2;
    const int ib  = ((px0 >> 18) * 3) << 18;
    const int hw0 = (px0 & (HW - 1)) + tid;
    #pragma unroll
    for (int k = 0; k < U2; ++k) {
        int hw = hw0 + k * BLK;
        p.r[k] = __ldg(img + ib + hw);
        p.g[k] = __ldg(img + ib + HW + hw);
        p.b[k] = __ldg(img + ib + 2 * HW + hw);
    }
    return p;
}

__device__ __forceinline__ void proc1(const __half2* __restrict__ st,
                                      float* __restrict__ out,
                                      int blk, int tid, const Px1& p)
{
    const int px0 = blk * STEP1;
    const int ib  = ((px0 >> 18) * 3) << 18;
    const int hw0 = (px0 & (HW - 1)) + tid;

    // Phase A: all coords.
    int base[U1]; float wx[U1], wy[U1], wz[U1];
    #pragma unroll
    for (int k = 0; k < U1; ++k)
        coords(p.r[k], p.g[k], p.b[k], base[k], wx[k], wy[k], wz[k]);

    // Phase B: all 16 LDS issued back-to-back (max smem-MLP).
    __half2 q[U1][8];
    #pragma unroll
    for (int k = 0; k < U1; ++k) {
        int bse = base[k];
        q[k][0] = st[bse];          q[k][1] = st[bse + 1];
        q[k][2] = st[bse + D];      q[k][3] = st[bse + D + 1];
        q[k][4] = st[bse + DD];     q[k][5] = st[bse + DD + 1];
        q[k][6] = st[bse + DD + D]; q[k][7] = st[bse + DD + D + 1];
    }

    // Phase C: math + stores.
    #pragma unroll
    for (int k = 0; k < U1; ++k) {
        float2 p000 = __half22float2(q[k][0]);
        float2 p001 = __half22float2(q[k][1]);
        float2 p010 = __half22float2(q[k][2]);
        float2 p011 = __half22float2(q[k][3]);
        float2 p100 = __half22float2(q[k][4]);
        float2 p101 = __half22float2(q[k][5]);
        float2 p110 = __half22float2(q[k][6]);
        float2 p111 = __half22float2(q[k][7]);

        float a00 = fmaf(wx[k], p001.x - p000.x, p000.x);
        float a01 = fmaf(wx[k], p011.x - p010.x, p010.x);
        float a10 = fmaf(wx[k], p101.x - p100.x, p100.x);
        float a11 = fmaf(wx[k], p111.x - p110.x, p110.x);
        float b0  = fmaf(wy[k], a01 - a00, a00);
        float b1  = fmaf(wy[k], a11 - a10, a10);
        float r0  = fmaf(wz[k], b1 - b0, b0);

        a00 = fmaf(wx[k], p001.y - p000.y, p000.y);
        a01 = fmaf(wx[k], p011.y - p010.y, p010.y);
        a10 = fmaf(wx[k], p101.y - p100.y, p100.y);
        a11 = fmaf(wx[k], p111.y - p110.y, p110.y);
        b0  = fmaf(wy[k], a01 - a00, a00);
        b1  = fmaf(wy[k], a11 - a10, a10);
        float r1 = fmaf(wz[k], b1 - b0, b0);

        int hw = hw0 + k * BLK;
        __stcs(out + ib + hw, r0);             // c=0 plane
        __stcs(out + ib + HW + hw, r1);        // c=1 plane
    }
}

__device__ __forceinline__ void proc2(const __half2* __restrict__ st,
                                      float* __restrict__ out,
                                      int blk, int tid, const Px2& p)
{
    const int px0 = blk * STEP2;
    const int ib  = ((px0 >> 18) * 3) << 18;
    const int hw0 = (px0 & (HW - 1)) + tid;

    // Phase A: all coords.
    int base[U2]; float wx[U2], wy[U2], wz[U2];
    #pragma unroll
    for (int k = 0; k < U2; ++k)
        coords(p.r[k], p.g[k], p.b[k], base[k], wx[k], wy[k], wz[k]);

    // Phase B: all 16 LDS issued back-to-back.
    __half2 q[U2][4];
    #pragma unroll
    for (int k = 0; k < U2; ++k) {
        int bse = base[k];
        q[k][0] = st[bse];          // (v, v_next - v)
        q[k][1] = st[bse + D];
        q[k][2] = st[bse + DD];
        q[k][3] = st[bse + DD + D];
    }

    // Phase C: math + stores.
    #pragma unroll
    for (int k = 0; k < U2; ++k) {
        float2 e00 = __half22float2(q[k][0]);
        float2 e01 = __half22float2(q[k][1]);
        float2 e10 = __half22float2(q[k][2]);
        float2 e11 = __half22float2(q[k][3]);

        float a00 = fmaf(wx[k], e00.y, e00.x);
        float a01 = fmaf(wx[k], e01.y, e01.x);
        float a10 = fmaf(wx[k], e10.y, e10.x);
        float a11 = fmaf(wx[k], e11.y, e11.x);
        float b0  = fmaf(wy[k], a01 - a00, a00);
        float b1  = fmaf(wy[k], a11 - a10, a10);

        __stcs(out + ib + 2 * HW + hw0 + k * BLK,
               fmaf(wz[k], b1 - b0, b0));      // c=2 plane
    }
}

__global__ __launch_bounds__(BLK, 1)
void trilerp_kernel(const float* __restrict__ lut,
                    const float* __restrict__ img,
                    float* __restrict__ out_full)   // = d_out (tuple base)
{
    extern __shared__ unsigned int sm[];
    const int tid = threadIdx.x;
    const int n1  = ((int)gridDim.x * 129) / 200;   // 98 of 152
    const bool is01 = (int)blockIdx.x < n1;
    float* out = out_full + 3 * D3;                 // trilerp output region

    // LUT passthrough (grid-strided; ~0.7 elements/thread).
    for (int j = blockIdx.x * BLK + tid; j < 3 * D3; j += (int)gridDim.x * BLK)
        out_full[j] = __ldg(lut + j);

    // Stage + convert this group's table. Batched: 36 LDG pairs issued in
    // unrolled groups so the L2 latency pipelines instead of serializing.
    if (is01) {
        #pragma unroll 8
        for (int i = tid; i < D3; i += BLK) {
            __half2 h = __floats2half2_rn(__ldg(lut + i), __ldg(lut + D3 + i));
            sm[i] = *reinterpret_cast<unsigned int*>(&h);
        }
    } else {
        #pragma unroll 8
        for (int i = tid; i < D3; i += BLK) {
            float v  = __ldg(lut + 2 * D3 + i);
            float vn = (i + 1 < D3) ? __ldg(lut + 2 * D3 + i + 1) : v;
            __half2 h = __floats2half2_rn(v, vn - v);
            sm[i] = *reinterpret_cast<unsigned int*>(&h);
        }
    }

    if (is01) {
        int blk = blockIdx.x;
        if (blk < NB1) {
            Px1 cur = load1(img, blk, tid);   // prefetch BEFORE barrier
            __syncthreads();
            const __half2* st = reinterpret_cast<const __half2*>(sm);
            int nxt = blk + n1;
            while (nxt < NB1) {
                Px1 pre = load1(img, nxt, tid);   // prefetch next block
                proc1(st, out, blk, tid, cur);    // process current
                cur = pre;
                blk = nxt;
                nxt += n1;
            }
            proc1(st, out, blk, tid, cur);
        } else {
            __syncthreads();
        }
    } else {
        const int n2 = (int)gridDim.x - n1;
        int blk = blockIdx.x - n1;
        if (blk < NB2) {
            Px2 cur = load2(img, blk, tid);   // prefetch BEFORE barrier
            __syncthreads();
            const __half2* st = reinterpret_cast<const __half2*>(sm);
            int nxt = blk + n2;
            while (nxt < NB2) {
                Px2 pre = load2(img, nxt, tid);
                proc2(st, out, blk, tid, cur);
                cur = pre;
                blk = nxt;
                nxt += n2;
            }
            proc2(st, out, blk, tid, cur);
        } else {
            __syncthreads();
        }
    }
}

extern "C" void kernel_launch(void* const* d_in, const int* in_sizes, int n_in,
                              void* d_out, int out_size)
{
    const float* lut = (const float*)d_in[0];
    const float* img = (const float*)d_in[1];
    if (n_in >= 2 && in_sizes[0] > in_sizes[1]) {   // defensive input-order check
        lut = (const float*)d_in[1];
        img = (const float*)d_in[0];
    }
    float* out = (float*)d_out;

    cudaFuncSetAttribute(trilerp_kernel,
                         cudaFuncAttributeMaxDynamicSharedMemorySize, SMEM_BYTES);

    int sms = 148;
    cudaDeviceGetAttribute(&sms, cudaDevAttrMultiProcessorCount, 0);

    trilerp_kernel<<<sms, BLK, SMEM_BYTES>>>(lut, img, out);
}